// round 15
// baseline (speedup 1.0000x reference)
#include <cuda_runtime.h>
#include <cuda_fp16.h>
#include <cstdint>

#define NN      10000
#define EE      30000
#define FEDGE   8
#define EMB     64
#define HID     16
#define NG      64
#define NCOL    1088   // 1024 P | 64 Q
#define QOFF    1024

// PDL: programmatic dependent launch (sm_90+ base PTX, graph-capturable)
#define GDC_WAIT()   asm volatile("griddepcontrol.wait;" ::: "memory")
#define GDC_LAUNCH() asm volatile("griddepcontrol.launch_dependents;" ::: "memory")

// ---------------- scratch (device globals) --------------------------------
__device__ __align__(128) float g_h0[EE * HID];
__device__ __align__(128) float g_h1[EE * HID];
__device__ __align__(128) float g_PQ[(size_t)NN * NCOL];
// agg buffers double as root-product init: gemm tile-17 writes x@root into
// the NEXT conv's agg, edge_msg accumulates messages on top.
__device__ __align__(128) float g_agg0[NN * EMB];
__device__ __align__(128) float g_agg1[NN * EMB];
__device__ __align__(128) float g_agg2[NN * EMB];
__device__ __align__(128) float g_pool[NG * EMB];

// ---------------- helpers --------------------------------------------------
__device__ __forceinline__ uint32_t smem_u32(const void* p) {
    uint32_t a;
    asm("{ .reg .u64 t; cvta.to.shared.u64 t, %1; cvt.u32.u64 %0, t; }" : "=r"(a) : "l"(p));
    return a;
}
__device__ __forceinline__ void ldmx4(uint32_t* r, uint32_t addr) {
    asm volatile("ldmatrix.sync.aligned.m8n8.x4.shared.b16 {%0,%1,%2,%3}, [%4];"
        : "=r"(r[0]), "=r"(r[1]), "=r"(r[2]), "=r"(r[3]) : "r"(addr));
}
__device__ __forceinline__ void mma_fp16(float* d, const uint32_t* a,
                                         uint32_t b0, uint32_t b1) {
    asm volatile("mma.sync.aligned.m16n8k16.row.col.f32.f16.f16.f32 "
        "{%0,%1,%2,%3}, {%4,%5,%6,%7}, {%8,%9}, {%0,%1,%2,%3};"
        : "+f"(d[0]), "+f"(d[1]), "+f"(d[2]), "+f"(d[3])
        : "r"(a[0]), "r"(a[1]), "r"(a[2]), "r"(a[3]), "r"(b0), "r"(b1));
}
__device__ __forceinline__ uint32_t pack_h2(float x, float y) {
    __half2 h = __floats2half2_rn(x, y);
    return *reinterpret_cast<uint32_t*>(&h);
}
__device__ __forceinline__ void split_h2(float x, float y,
                                         uint32_t& hi, uint32_t& lo) {
    __half hx = __float2half_rn(x), hy = __float2half_rn(y);
    __half lx = __float2half_rn(x - __half2float(hx));
    __half ly = __float2half_rn(y - __half2float(hy));
    hi = ((uint32_t)__half_as_ushort(hy) << 16) | __half_as_ushort(hx);
    lo = ((uint32_t)__half_as_ushort(ly) << 16) | __half_as_ushort(lx);
}

// ---------------- prep: edge MLP hiddens only ------------------------------
#define EH_BLOCKS ((EE + 255) / 256)

__global__ __launch_bounds__(256) void prep_kernel(
    const float* __restrict__ ea,
    const float* __restrict__ nn0_w1, const float* __restrict__ nn0_b1,
    const float* __restrict__ nn1_w1, const float* __restrict__ nn1_b1)
{
    // release gemm32 immediately: it depends only on kernel inputs, not on
    // g_h*. Its own GDC_WAIT at kernel end re-establishes the grandchild
    // ordering (edge0 not released until this kernel's writes are complete).
    GDC_LAUNCH();

    int tid = threadIdx.x;
    __shared__ float sw0[FEDGE * HID], sw1[FEDGE * HID];
    __shared__ float sb0[HID], sb1[HID];
    if (tid < FEDGE * HID) { sw0[tid] = nn0_w1[tid]; sw1[tid] = nn1_w1[tid]; }
    if (tid < HID)         { sb0[tid] = nn0_b1[tid]; sb1[tid] = nn1_b1[tid]; }
    __syncthreads();

    int e = blockIdx.x * 256 + tid;
    if (e >= EE) return;
    const float4* p = reinterpret_cast<const float4*>(ea + (size_t)e * FEDGE);
    float4 v0 = p[0], v1 = p[1];
    float a[8] = {v0.x, v0.y, v0.z, v0.w, v1.x, v1.y, v1.z, v1.w};
#pragma unroll
    for (int h = 0; h < HID; h++) {
        float s0 = sb0[h], s1 = sb1[h];
#pragma unroll
        for (int j = 0; j < FEDGE; j++) {
            s0 += a[j] * sw0[j * HID + h];
            s1 += a[j] * sw1[j * HID + h];
        }
        g_h0[e * HID + h] = fmaxf(s0, 0.f);
        g_h1[e * HID + h] = fmaxf(s1, 0.f);
    }
}

// ---------------- fused HMMA GEMM (fp16: A hi-only, B hi/lo, 2 products) ---
// A = [x | relu(agg+bias)] (128 rows), B[r][k] = base[k*64+r] staged directly
// from w2/b2/root (no transpose prep). Tiles 0..16 -> g_PQ, tile 17 (root
// product) -> NEXT conv's agg init.
// MODE 0: no data dep on prep -> GDC_WAIT/LAUNCH at kernel END (full overlap).
// MODE>=1: B0+bias staged pre-wait; A-stage needs parent agg.
template <int D, int MODE>
__global__ __launch_bounds__(256, 3) void gemm_fused_kernel(
    const float* __restrict__ xin, const float* __restrict__ biasin,
    const float* __restrict__ w2, const float* __restrict__ b2,
    const float* __restrict__ rootm)
{
    const int SD = D + 8;
    const int CPT = D / 8;
    extern __shared__ ushort smu[];
    ushort* Ah = smu;                    // 128*SD (hi only)
    ushort* Bh = Ah + 128 * SD;          // 64*SD
    ushort* Bl = Bh + 64 * SD;           // 64*SD
    __shared__ float sbias[64];

    const float* __restrict__ aggin = (MODE == 1) ? g_agg0 : g_agg1;
    float* __restrict__ aggout = (MODE == 0) ? g_agg0 : (MODE == 1 ? g_agg1 : g_agg2);

    int tid = threadIdx.x, wid = tid >> 5, l = tid & 31;
    int wm = wid & 3, wn = wid >> 2;
    int m0 = blockIdx.y * 128;
    int t0 = blockIdx.x * 2;

    // stage B[r][k] = base[k*64 + r]; lanes sweep r (coalesced 256B lines).
    auto stageB = [&](int ct) {
        const float* __restrict__ base =
            (ct < 16) ? (w2 + (size_t)ct * (D * 64)) : (ct == 16 ? b2 : rootm);
        int r = tid & 63;
        const int KPT = D / 4;            // k's per thread
        int k0 = (tid >> 6) * KPT;
        uint32_t* bh32 = reinterpret_cast<uint32_t*>(Bh);
        uint32_t* bl32 = reinterpret_cast<uint32_t*>(Bl);
#pragma unroll
        for (int j = 0; j < KPT / 2; j++) {
            int k = k0 + 2 * j;
            float x = base[(size_t)k * 64 + r];
            float y = base[(size_t)(k + 1) * 64 + r];
            uint32_t hi, lo;
            split_h2(x, y, hi, lo);
            int bix = (r * SD + k) >> 1;
            bh32[bix] = hi;
            bl32[bix] = lo;
        }
    };

    if (MODE) {
        // pre-wait prologue: inputs only
        if (tid < 64) sbias[tid] = biasin[tid];
        stageB(t0);
        GDC_WAIT();
        GDC_LAUNCH();
        __syncthreads();          // sbias + B0 visible before A-stage
    }

    // ---- stage A once (full D), fp32 -> fp16 hi only ----
    for (int idx = tid; idx < 128 * CPT; idx += 256) {
        int r = idx / CPT, cb = (idx % CPT) * 8;
        int n = m0 + r;
        bool v = (n < NN);
        float vals[8];
        if (MODE == 0) {
            float4 a0 = make_float4(0.f, 0.f, 0.f, 0.f), a1 = a0;
            if (v) {
                a0 = *reinterpret_cast<const float4*>(xin + (size_t)n * D + cb);
                a1 = *reinterpret_cast<const float4*>(xin + (size_t)n * D + cb + 4);
            }
            vals[0]=a0.x; vals[1]=a0.y; vals[2]=a0.z; vals[3]=a0.w;
            vals[4]=a1.x; vals[5]=a1.y; vals[6]=a1.z; vals[7]=a1.w;
        } else {
            float4 g0 = make_float4(0.f,0.f,0.f,0.f), g1 = g0;
            if (v) {
                g0 = *reinterpret_cast<const float4*>(aggin + (size_t)n * EMB + cb);
                g1 = *reinterpret_cast<const float4*>(aggin + (size_t)n * EMB + cb + 4);
            }
            vals[0] = fmaxf(g0.x + sbias[cb+0], 0.f);
            vals[1] = fmaxf(g0.y + sbias[cb+1], 0.f);
            vals[2] = fmaxf(g0.z + sbias[cb+2], 0.f);
            vals[3] = fmaxf(g0.w + sbias[cb+3], 0.f);
            vals[4] = fmaxf(g1.x + sbias[cb+4], 0.f);
            vals[5] = fmaxf(g1.y + sbias[cb+5], 0.f);
            vals[6] = fmaxf(g1.z + sbias[cb+6], 0.f);
            vals[7] = fmaxf(g1.w + sbias[cb+7], 0.f);
        }
        uint32_t* ah32 = reinterpret_cast<uint32_t*>(Ah);
        int base = (r * SD + cb) >> 1;
#pragma unroll
        for (int j = 0; j < 4; j++)
            ah32[base + j] = pack_h2(vals[2*j], vals[2*j+1]);
    }

    uint32_t aAh = smem_u32(Ah);
    uint32_t aBh = smem_u32(Bh), aBl = smem_u32(Bl);

#pragma unroll
    for (int ti = 0; ti < 2; ti++) {
        int ct = t0 + ti;
        if (!(MODE && ti == 0)) stageB(ct);   // B0 already staged for MODE>=1
        __syncthreads();   // covers A-stage (+ B-stage this iter)

        float acc[2][4][4];
#pragma unroll
        for (int mi = 0; mi < 2; mi++)
#pragma unroll
            for (int nf = 0; nf < 4; nf++)
#pragma unroll
                for (int q = 0; q < 4; q++) acc[mi][nf][q] = 0.f;

#pragma unroll
        for (int ks = 0; ks < D; ks += 16) {
            uint32_t ahf[2][4];
#pragma unroll
            for (int mi = 0; mi < 2; mi++) {
                uint32_t off = ((uint32_t)(wm * 32 + mi * 16 + (l & 15)) * SD
                                + ks + (l >> 4) * 8) * 2;
                ldmx4(ahf[mi], aAh + off);
            }
            uint32_t bhf[8], blf[8];
#pragma unroll
            for (int g = 0; g < 2; g++) {
                uint32_t off = ((uint32_t)(wn * 32 + g * 16 + (l & 7) + ((l >> 4) & 1) * 8) * SD
                                + ks + ((l >> 3) & 1) * 8) * 2;
                ldmx4(bhf + g * 4, aBh + off);
                ldmx4(blf + g * 4, aBl + off);
            }
#pragma unroll
            for (int mi = 0; mi < 2; mi++)
#pragma unroll
                for (int nf = 0; nf < 4; nf++) {
                    mma_fp16(acc[mi][nf], ahf[mi], bhf[nf*2], bhf[nf*2+1]);
                    mma_fp16(acc[mi][nf], ahf[mi], blf[nf*2], blf[nf*2+1]);
                }
        }

        // ---- writeback: P,Q tiles -> g_PQ ; root tile -> next agg init ----
#pragma unroll
        for (int mi = 0; mi < 2; mi++)
#pragma unroll
            for (int nf = 0; nf < 4; nf++) {
                int gr = m0 + wm * 32 + mi * 16 + (l >> 2);
                int co = ct * 64 + wn * 32 + nf * 8 + 2 * (l & 3);
                float2 v0 = make_float2(acc[mi][nf][0], acc[mi][nf][1]);
                float2 v1 = make_float2(acc[mi][nf][2], acc[mi][nf][3]);
                if (ct < 17) {
                    if (gr < NN)
                        *reinterpret_cast<float2*>(g_PQ + (size_t)gr * NCOL + co) = v0;
                    if (gr + 8 < NN)
                        *reinterpret_cast<float2*>(g_PQ + (size_t)(gr + 8) * NCOL + co) = v1;
                } else {
                    int cr = co - NCOL;
                    if (gr < NN)
                        *reinterpret_cast<float2*>(aggout + (size_t)gr * EMB + cr) = v0;
                    if (gr + 8 < NN)
                        *reinterpret_cast<float2*>(aggout + (size_t)(gr + 8) * EMB + cr) = v1;
                }
            }
        __syncthreads();
    }

    if (MODE == 0) {
        // ran fully concurrent with prep; re-establish ordering for edge0
        GDC_WAIT();
        GDC_LAUNCH();
    }
}

// ---------------- per-edge message + scatter (2 edges/warp, vec, PDL) ------
__global__ __launch_bounds__(256) void edge_msg_kernel(const int* __restrict__ ei, int conv)
{
    int gw   = (blockIdx.x * 256 + threadIdx.x) >> 5;
    int lane = threadIdx.x & 31;
    int e    = gw * 2 + (lane >> 4);
    int sub  = lane & 15;

    const float* __restrict__ hsrc = conv ? g_h1 : g_h0;
    float* __restrict__ agg = (conv == 0) ? g_agg0 : (conv == 1 ? g_agg1 : g_agg2);

    // pre-wait prologue: edge index + h loads (inputs / grandparent-complete)
    bool act = (e < EE);
    int src = 0, dst = 0;
    float hv = 0.f;
    if (act) {
        src = ei[e];
        dst = ei[EE + e];
        hv  = hsrc[(size_t)e * HID + sub];
    }
    GDC_WAIT();
    GDC_LAUNCH();
    if (!act) return;

    const float* __restrict__ P = g_PQ + (size_t)src * NCOL;
    float4 acc = *reinterpret_cast<const float4*>(P + QOFF + sub * 4);
#pragma unroll
    for (int h = 0; h < HID; h++) {
        float w = __shfl_sync(0xffffffffu, hv, (lane & 16) | h);
        float4 f = *reinterpret_cast<const float4*>(P + h * EMB + sub * 4);
        acc.x += w * f.x; acc.y += w * f.y; acc.z += w * f.z; acc.w += w * f.w;
    }
    float* a = agg + (size_t)dst * EMB + sub * 4;
    asm volatile("red.global.add.v4.f32 [%0], {%1,%2,%3,%4};"
                 :: "l"(a), "f"(acc.x), "f"(acc.y), "f"(acc.z), "f"(acc.w)
                 : "memory");
}

// ---------------- pool (fused final combine; batch sorted, x >= 0) --------
__global__ __launch_bounds__(256) void pool_kernel(const int* __restrict__ batch,
                                                   const float* __restrict__ bias2)
{
    int tid = threadIdx.x;
    int o = tid & 63, seg = tid >> 6;
    int n0 = blockIdx.x * 32 + seg * 8;
    float bz = __ldg(bias2 + o);
    GDC_WAIT();
    GDC_LAUNCH();
    int curb = -1;
    float m = 0.f;
    for (int k = 0; k < 8; k++) {
        int n = n0 + k;
        if (n >= NN) break;
        int b = batch[n];
        if (b != curb) {
            if (curb >= 0)
                atomicMax(reinterpret_cast<unsigned*>(g_pool + (size_t)curb * EMB + o),
                          __float_as_uint(m));
            curb = b;
            m = 0.f;
        }
        float x = fmaxf(g_agg2[(size_t)n * EMB + o] + bz, 0.f);
        m = fmaxf(m, x);
    }
    if (curb >= 0)
        atomicMax(reinterpret_cast<unsigned*>(g_pool + (size_t)curb * EMB + o),
                  __float_as_uint(m));
}

// ---------------- head -----------------------------------------------------
__global__ __launch_bounds__(64) void head_kernel(
    const float* __restrict__ lin0w, const float* __restrict__ lin0b,
    const float* __restrict__ lin1w, const float* __restrict__ lin1b,
    float* __restrict__ out)
{
    __shared__ float pg[EMB];
    __shared__ float red[EMB];
    int g = blockIdx.x, o = threadIdx.x;
    float bo = lin0b[o];          // pre-wait: inputs only
    float w1 = lin1w[o];
    GDC_WAIT();
    pg[o] = g_pool[(size_t)g * EMB + o];
    __syncthreads();

    float h = bo;
#pragma unroll
    for (int i = 0; i < EMB; i++) h += pg[i] * lin0w[i * EMB + o];
    red[o] = h * w1;
    __syncthreads();
#pragma unroll
    for (int s = 32; s > 0; s >>= 1) {
        if (o < s) red[o] += red[o + s];
        __syncthreads();
    }
    if (o == 0) out[g] = red[0] + lin1b[0];
}

// ---------------- PDL launch helper ----------------------------------------
template <typename... Args>
static void launch_pdl(void (*func)(Args...), dim3 grid, dim3 block,
                       size_t smem, Args... args)
{
    cudaLaunchConfig_t cfg = {};
    cfg.gridDim = grid;
    cfg.blockDim = block;
    cfg.dynamicSmemBytes = smem;
    cfg.stream = 0;
    cudaLaunchAttribute attr[1];
    attr[0].id = cudaLaunchAttributeProgrammaticStreamSerialization;
    attr[0].val.programmaticStreamSerializationAllowed = 1;
    cfg.attrs = attr;
    cfg.numAttrs = 1;
    cudaLaunchKernelEx(&cfg, func, args...);
}

// ---------------- launch ----------------------------------------------------
extern "C" void kernel_launch(void* const* d_in, const int* in_sizes, int n_in,
                              void* d_out, int out_size)
{
    const float* x_p    = (const float*)d_in[0];
    const float* ea     = (const float*)d_in[2];
    const int*   ei     = (const int*)  d_in[4];
    const int*   batch  = (const int*)  d_in[5];
    const float* nn0_w1 = (const float*)d_in[6];
    const float* nn0_b1 = (const float*)d_in[7];
    const float* nn0_w2 = (const float*)d_in[8];
    const float* nn0_b2 = (const float*)d_in[9];
    const float* nn1_w1 = (const float*)d_in[10];
    const float* nn1_b1 = (const float*)d_in[11];
    const float* nn1_w2 = (const float*)d_in[12];
    const float* nn1_b2 = (const float*)d_in[13];
    const float* root0  = (const float*)d_in[14];
    const float* bias0  = (const float*)d_in[15];
    const float* root1  = (const float*)d_in[16];
    const float* bias1  = (const float*)d_in[17];
    const float* root2  = (const float*)d_in[18];
    const float* bias2  = (const float*)d_in[19];
    const float* lin0_w = (const float*)d_in[20];
    const float* lin0_b = (const float*)d_in[21];
    const float* lin1_w = (const float*)d_in[22];
    const float* lin1_b = (const float*)d_in[23];
    float* out = (float*)d_out;

    // smem: A(hi) 128*SD*2 + B(hi+lo) 2*64*SD*2 bytes
    size_t smem32 = 128 * 40 * 2 + 2 * 64 * 40 * 2;   // 20480
    size_t smem64 = 128 * 72 * 2 + 2 * 64 * 72 * 2;   // 36864

    dim3 gemm_grid(9, (NN + 127) / 128);
    int msg_blocks = EE / 16;

    prep_kernel<<<EH_BLOCKS, 256>>>(ea, nn0_w1, nn0_b1, nn1_w1, nn1_b1);

    // ---- conv0 (overlaps prep; PDL wait at kernel end) ----
    launch_pdl(gemm_fused_kernel<32, 0>, gemm_grid, dim3(256), smem32,
               x_p, bias0, nn0_w2, nn0_b2, root0);
    launch_pdl(edge_msg_kernel, dim3(msg_blocks), dim3(256), (size_t)0, ei, 0);

    // ---- conv1 ----
    launch_pdl(gemm_fused_kernel<64, 1>, gemm_grid, dim3(256), smem64,
               (const float*)nullptr, bias0, nn1_w2, nn1_b2, root1);
    launch_pdl(edge_msg_kernel, dim3(msg_blocks), dim3(256), (size_t)0, ei, 1);

    // ---- conv2 ----
    launch_pdl(gemm_fused_kernel<64, 2>, gemm_grid, dim3(256), smem64,
               (const float*)nullptr, bias1, nn1_w2, nn1_b2, root2);
    launch_pdl(edge_msg_kernel, dim3(msg_blocks), dim3(256), (size_t)0, ei, 2);

    // ---- pool (fused final combine) + head ----
    launch_pdl(pool_kernel, dim3((NN + 31) / 32), dim3(256), (size_t)0, batch, bias2);
    launch_pdl(head_kernel, dim3(NG), dim3(64), (size_t)0,
               lin0_w, lin0_b, lin1_w, lin1_b, out);
}

// round 16
// speedup vs baseline: 1.0038x; 1.0038x over previous
#include <cuda_runtime.h>
#include <cuda_fp16.h>
#include <cstdint>

#define NN      10000
#define EE      30000
#define FEDGE   8
#define EMB     64
#define HID     16
#define NG      64
#define NCOL    1088   // 1024 P | 64 Q
#define QOFF    1024

// PDL: programmatic dependent launch (sm_90+ base PTX, graph-capturable)
#define GDC_WAIT()   asm volatile("griddepcontrol.wait;" ::: "memory")
#define GDC_LAUNCH() asm volatile("griddepcontrol.launch_dependents;" ::: "memory")

// ---------------- scratch (device globals) --------------------------------
__device__ __align__(128) float g_h0[EE * HID];
__device__ __align__(128) float g_h1[EE * HID];
__device__ __align__(128) float g_PQ[(size_t)NN * NCOL];
// agg buffers double as root-product init: gemm tile-17 writes x@root into
// the NEXT conv's agg, edge_msg accumulates messages on top.
__device__ __align__(128) float g_agg0[NN * EMB];
__device__ __align__(128) float g_agg1[NN * EMB];
__device__ __align__(128) float g_agg2[NN * EMB];
__device__ __align__(128) float g_WT0[NCOL * 32];  // [c][i] P+Q, conv0
__device__ __align__(128) float g_WT1[NCOL * 64];  // [c][i] P+Q, convs 1&2
__device__ __align__(128) float g_RT0[64 * 32];    // [o][i] rootT
__device__ __align__(128) float g_RT1[64 * 64];
__device__ __align__(128) float g_RT2[64 * 64];
__device__ __align__(128) float g_pool[NG * EMB];

// ---------------- helpers --------------------------------------------------
__device__ __forceinline__ uint32_t smem_u32(const void* p) {
    uint32_t a;
    asm("{ .reg .u64 t; cvta.to.shared.u64 t, %1; cvt.u32.u64 %0, t; }" : "=r"(a) : "l"(p));
    return a;
}
__device__ __forceinline__ void ldmx4(uint32_t* r, uint32_t addr) {
    asm volatile("ldmatrix.sync.aligned.m8n8.x4.shared.b16 {%0,%1,%2,%3}, [%4];"
        : "=r"(r[0]), "=r"(r[1]), "=r"(r[2]), "=r"(r[3]) : "r"(addr));
}
__device__ __forceinline__ void mma_fp16(float* d, const uint32_t* a,
                                         uint32_t b0, uint32_t b1) {
    asm volatile("mma.sync.aligned.m16n8k16.row.col.f32.f16.f16.f32 "
        "{%0,%1,%2,%3}, {%4,%5,%6,%7}, {%8,%9}, {%0,%1,%2,%3};"
        : "+f"(d[0]), "+f"(d[1]), "+f"(d[2]), "+f"(d[3])
        : "r"(a[0]), "r"(a[1]), "r"(a[2]), "r"(a[3]), "r"(b0), "r"(b1));
}
__device__ __forceinline__ uint32_t pack_h2(float x, float y) {
    __half2 h = __floats2half2_rn(x, y);
    return *reinterpret_cast<uint32_t*>(&h);
}
__device__ __forceinline__ void split_h2(float x, float y,
                                         uint32_t& hi, uint32_t& lo) {
    __half hx = __float2half_rn(x), hy = __float2half_rn(y);
    __half lx = __float2half_rn(x - __half2float(hx));
    __half ly = __float2half_rn(y - __half2float(hy));
    hi = ((uint32_t)__half_as_ushort(hy) << 16) | __half_as_ushort(hx);
    lo = ((uint32_t)__half_as_ushort(ly) << 16) | __half_as_ushort(lx);
}

// ---------------- prep: transposes + edge MLP hiddens ----------------------
#define TR_BLOCKS 37
#define EH_BLOCKS ((EE + 255) / 256)

__global__ __launch_bounds__(256) void prep_kernel(
    const float* __restrict__ ea,
    const float* __restrict__ nn0_w1, const float* __restrict__ nn0_b1,
    const float* __restrict__ nn0_w2, const float* __restrict__ nn0_b2,
    const float* __restrict__ nn1_w1, const float* __restrict__ nn1_b1,
    const float* __restrict__ nn1_w2, const float* __restrict__ nn1_b2,
    const float* __restrict__ root0, const float* __restrict__ root1,
    const float* __restrict__ root2)
{
    // release gemm32 immediately: its pre-wait phase reads inputs only;
    // its GDC_WAIT (before B reads) re-establishes ordering on g_WT0/g_RT0.
    GDC_LAUNCH();

    int tid = threadIdx.x;
    int b = blockIdx.x;

    if (b < TR_BLOCKS) {
        __shared__ float ts[64 * 65];
        const float* src;
        float* dst;
        int D;
        if (b < 17)       { D = 32; src = (b < 16) ? nn0_w2 + b * 2048 : nn0_b2;
                            dst = g_WT0 + b * 64 * 32; }
        else if (b == 17) { D = 32; src = root0; dst = g_RT0; }
        else if (b < 35)  { int bb = b - 18; D = 64;
                            src = (bb < 16) ? nn1_w2 + bb * 4096 : nn1_b2;
                            dst = g_WT1 + bb * 64 * 64; }
        else if (b == 35) { D = 64; src = root1; dst = g_RT1; }
        else              { D = 64; src = root2; dst = g_RT2; }

        for (int idx = tid; idx < 64 * D; idx += 256) {
            int o = idx & 63, i = idx >> 6;
            ts[o * 65 + i] = src[i * 64 + o];
        }
        __syncthreads();
        for (int idx = tid; idx < 64 * D; idx += 256) {
            int i = idx & (D - 1), o = idx / D;
            dst[idx] = ts[o * 65 + i];
        }
        return;
    }

    __shared__ float sw0[FEDGE * HID], sw1[FEDGE * HID];
    __shared__ float sb0[HID], sb1[HID];
    if (tid < FEDGE * HID) { sw0[tid] = nn0_w1[tid]; sw1[tid] = nn1_w1[tid]; }
    if (tid < HID)         { sb0[tid] = nn0_b1[tid]; sb1[tid] = nn1_b1[tid]; }
    __syncthreads();

    int e = (b - TR_BLOCKS) * 256 + tid;
    if (e >= EE) return;
    const float4* p = reinterpret_cast<const float4*>(ea + (size_t)e * FEDGE);
    float4 v0 = p[0], v1 = p[1];
    float a[8] = {v0.x, v0.y, v0.z, v0.w, v1.x, v1.y, v1.z, v1.w};
#pragma unroll
    for (int h = 0; h < HID; h++) {
        float s0 = sb0[h], s1 = sb1[h];
#pragma unroll
        for (int j = 0; j < FEDGE; j++) {
            s0 += a[j] * sw0[j * HID + h];
            s1 += a[j] * sw1[j * HID + h];
        }
        g_h0[e * HID + h] = fmaxf(s0, 0.f);
        g_h1[e * HID + h] = fmaxf(s1, 0.f);
    }
}

// ---------------- fused HMMA GEMM (fp16: A hi-only, B hi/lo, 2 products) ---
// A = [x | relu(agg+bias)] (128 rows), B = WT^T, 2 column tiles per block.
// Tiles 0..16 -> g_PQ, tile 17 (root product) -> NEXT conv's agg init.
// MODE 0: A-stage (input-only) pre-wait; GDC_WAIT before first B read.
// MODE>=1: B0+bias (prep data) pre-wait; A-stage needs the parent's agg.
template <int D, int MODE>
__global__ __launch_bounds__(256, 3) void gemm_fused_kernel(
    const float* __restrict__ xin, const float* __restrict__ biasin)
{
    const int SD = D + 8;
    const int CPT = D / 8;
    extern __shared__ ushort smu[];
    ushort* Ah = smu;                    // 128*SD (hi only)
    ushort* Bh = Ah + 128 * SD;          // 64*SD
    ushort* Bl = Bh + 64 * SD;           // 64*SD
    __shared__ float sbias[64];

    const float* __restrict__ aggin = (MODE == 1) ? g_agg0 : g_agg1;
    float* __restrict__ aggout = (MODE == 0) ? g_agg0 : (MODE == 1 ? g_agg1 : g_agg2);
    const float* __restrict__ WT = (MODE == 0) ? g_WT0 : g_WT1;
    const float* __restrict__ RT = (MODE == 0) ? g_RT0 : (MODE == 1 ? g_RT1 : g_RT2);

    int tid = threadIdx.x, wid = tid >> 5, l = tid & 31;
    int wm = wid & 3, wn = wid >> 2;
    int m0 = blockIdx.y * 128;
    int t0 = blockIdx.x * 2;

    auto stageB = [&](int ct) {
        const float* __restrict__ bsrc = (ct == 17) ? RT : WT + (size_t)ct * 64 * D;
        for (int idx = tid; idx < 64 * CPT; idx += 256) {
            int r = idx / CPT, cb = (idx % CPT) * 8;
            float4 b0 = *reinterpret_cast<const float4*>(bsrc + r * D + cb);
            float4 b1 = *reinterpret_cast<const float4*>(bsrc + r * D + cb + 4);
            float bv[8] = {b0.x,b0.y,b0.z,b0.w,b1.x,b1.y,b1.z,b1.w};
            uint32_t* bh32 = reinterpret_cast<uint32_t*>(Bh);
            uint32_t* bl32 = reinterpret_cast<uint32_t*>(Bl);
            int base = (r * SD + cb) >> 1;
#pragma unroll
            for (int j = 0; j < 4; j++) {
                uint32_t hi, lo;
                split_h2(bv[2*j], bv[2*j+1], hi, lo);
                bh32[base + j] = hi;
                bl32[base + j] = lo;
            }
        }
    };

    if (MODE) {
        // pre-wait prologue: prep outputs of the GRANDPARENT round (complete)
        if (tid < 64) sbias[tid] = biasin[tid];
        stageB(t0);
        GDC_WAIT();
        GDC_LAUNCH();
        __syncthreads();          // sbias + B0 visible before A-stage
    }

    // ---- stage A once (full D), fp32 -> fp16 hi only ----
    // MODE 0: reads xin (kernel input) -> safe pre-wait.
    for (int idx = tid; idx < 128 * CPT; idx += 256) {
        int r = idx / CPT, cb = (idx % CPT) * 8;
        int n = m0 + r;
        bool v = (n < NN);
        float vals[8];
        if (MODE == 0) {
            float4 a0 = make_float4(0.f, 0.f, 0.f, 0.f), a1 = a0;
            if (v) {
                a0 = *reinterpret_cast<const float4*>(xin + (size_t)n * D + cb);
                a1 = *reinterpret_cast<const float4*>(xin + (size_t)n * D + cb + 4);
            }
            vals[0]=a0.x; vals[1]=a0.y; vals[2]=a0.z; vals[3]=a0.w;
            vals[4]=a1.x; vals[5]=a1.y; vals[6]=a1.z; vals[7]=a1.w;
        } else {
            float4 g0 = make_float4(0.f,0.f,0.f,0.f), g1 = g0;
            if (v) {
                g0 = *reinterpret_cast<const float4*>(aggin + (size_t)n * EMB + cb);
                g1 = *reinterpret_cast<const float4*>(aggin + (size_t)n * EMB + cb + 4);
            }
            vals[0] = fmaxf(g0.x + sbias[cb+0], 0.f);
            vals[1] = fmaxf(g0.y + sbias[cb+1], 0.f);
            vals[2] = fmaxf(g0.z + sbias[cb+2], 0.f);
            vals[3] = fmaxf(g0.w + sbias[cb+3], 0.f);
            vals[4] = fmaxf(g1.x + sbias[cb+4], 0.f);
            vals[5] = fmaxf(g1.y + sbias[cb+5], 0.f);
            vals[6] = fmaxf(g1.z + sbias[cb+6], 0.f);
            vals[7] = fmaxf(g1.w + sbias[cb+7], 0.f);
        }
        uint32_t* ah32 = reinterpret_cast<uint32_t*>(Ah);
        int base = (r * SD + cb) >> 1;
#pragma unroll
        for (int j = 0; j < 4; j++)
            ah32[base + j] = pack_h2(vals[2*j], vals[2*j+1]);
    }

    if (MODE == 0) {
        // B sources (g_WT0/g_RT0) are written by prep -> wait before staging B
        GDC_WAIT();
        GDC_LAUNCH();
    }

    uint32_t aAh = smem_u32(Ah);
    uint32_t aBh = smem_u32(Bh), aBl = smem_u32(Bl);

#pragma unroll
    for (int ti = 0; ti < 2; ti++) {
        int ct = t0 + ti;
        if (!(MODE && ti == 0)) stageB(ct);   // B0 already staged for MODE>=1
        __syncthreads();   // covers A-stage (+ B-stage this iter)

        float acc[2][4][4];
#pragma unroll
        for (int mi = 0; mi < 2; mi++)
#pragma unroll
            for (int nf = 0; nf < 4; nf++)
#pragma unroll
                for (int q = 0; q < 4; q++) acc[mi][nf][q] = 0.f;

#pragma unroll
        for (int ks = 0; ks < D; ks += 16) {
            uint32_t ahf[2][4];
#pragma unroll
            for (int mi = 0; mi < 2; mi++) {
                uint32_t off = ((uint32_t)(wm * 32 + mi * 16 + (l & 15)) * SD
                                + ks + (l >> 4) * 8) * 2;
                ldmx4(ahf[mi], aAh + off);
            }
            uint32_t bhf[8], blf[8];
#pragma unroll
            for (int g = 0; g < 2; g++) {
                uint32_t off = ((uint32_t)(wn * 32 + g * 16 + (l & 7) + ((l >> 4) & 1) * 8) * SD
                                + ks + ((l >> 3) & 1) * 8) * 2;
                ldmx4(bhf + g * 4, aBh + off);
                ldmx4(blf + g * 4, aBl + off);
            }
#pragma unroll
            for (int mi = 0; mi < 2; mi++)
#pragma unroll
                for (int nf = 0; nf < 4; nf++) {
                    mma_fp16(acc[mi][nf], ahf[mi], bhf[nf*2], bhf[nf*2+1]);
                    mma_fp16(acc[mi][nf], ahf[mi], blf[nf*2], blf[nf*2+1]);
                }
        }

        // ---- writeback: P,Q tiles -> g_PQ ; root tile -> next agg init ----
#pragma unroll
        for (int mi = 0; mi < 2; mi++)
#pragma unroll
            for (int nf = 0; nf < 4; nf++) {
                int gr = m0 + wm * 32 + mi * 16 + (l >> 2);
                int co = ct * 64 + wn * 32 + nf * 8 + 2 * (l & 3);
                float2 v0 = make_float2(acc[mi][nf][0], acc[mi][nf][1]);
                float2 v1 = make_float2(acc[mi][nf][2], acc[mi][nf][3]);
                if (ct < 17) {
                    if (gr < NN)
                        *reinterpret_cast<float2*>(g_PQ + (size_t)gr * NCOL + co) = v0;
                    if (gr + 8 < NN)
                        *reinterpret_cast<float2*>(g_PQ + (size_t)(gr + 8) * NCOL + co) = v1;
                } else {
                    int cr = co - NCOL;
                    if (gr < NN)
                        *reinterpret_cast<float2*>(aggout + (size_t)gr * EMB + cr) = v0;
                    if (gr + 8 < NN)
                        *reinterpret_cast<float2*>(aggout + (size_t)(gr + 8) * EMB + cr) = v1;
                }
            }
        __syncthreads();
    }
}

// ---------------- per-edge message + scatter (2 edges/warp, vec, PDL) ------
__global__ __launch_bounds__(256) void edge_msg_kernel(const int* __restrict__ ei, int conv)
{
    int gw   = (blockIdx.x * 256 + threadIdx.x) >> 5;
    int lane = threadIdx.x & 31;
    int e    = gw * 2 + (lane >> 4);
    int sub  = lane & 15;

    const float* __restrict__ hsrc = conv ? g_h1 : g_h0;
    float* __restrict__ agg = (conv == 0) ? g_agg0 : (conv == 1 ? g_agg1 : g_agg2);

    // pre-wait prologue: edge index + h loads (inputs / grandparent-complete)
    bool act = (e < EE);
    int src = 0, dst = 0;
    float hv = 0.f;
    if (act) {
        src = ei[e];
        dst = ei[EE + e];
        hv  = hsrc[(size_t)e * HID + sub];
    }
    GDC_WAIT();
    GDC_LAUNCH();
    if (!act) return;

    const float* __restrict__ P = g_PQ + (size_t)src * NCOL;
    float4 acc = *reinterpret_cast<const float4*>(P + QOFF + sub * 4);
#pragma unroll
    for (int h = 0; h < HID; h++) {
        float w = __shfl_sync(0xffffffffu, hv, (lane & 16) | h);
        float4 f = *reinterpret_cast<const float4*>(P + h * EMB + sub * 4);
        acc.x += w * f.x; acc.y += w * f.y; acc.z += w * f.z; acc.w += w * f.w;
    }
    float* a = agg + (size_t)dst * EMB + sub * 4;
    asm volatile("red.global.add.v4.f32 [%0], {%1,%2,%3,%4};"
                 :: "l"(a), "f"(acc.x), "f"(acc.y), "f"(acc.z), "f"(acc.w)
                 : "memory");
}

// ---------------- pool (fused final combine; batch sorted, x >= 0) --------
__global__ __launch_bounds__(256) void pool_kernel(const int* __restrict__ batch,
                                                   const float* __restrict__ bias2)
{
    int tid = threadIdx.x;
    int o = tid & 63, seg = tid >> 6;
    int n0 = blockIdx.x * 32 + seg * 8;
    float bz = __ldg(bias2 + o);
    GDC_WAIT();
    GDC_LAUNCH();
    int curb = -1;
    float m = 0.f;
    for (int k = 0; k < 8; k++) {
        int n = n0 + k;
        if (n >= NN) break;
        int b = batch[n];
        if (b != curb) {
            if (curb >= 0)
                atomicMax(reinterpret_cast<unsigned*>(g_pool + (size_t)curb * EMB + o),
                          __float_as_uint(m));
            curb = b;
            m = 0.f;
        }
        float x = fmaxf(g_agg2[(size_t)n * EMB + o] + bz, 0.f);
        m = fmaxf(m, x);
    }
    if (curb >= 0)
        atomicMax(reinterpret_cast<unsigned*>(g_pool + (size_t)curb * EMB + o),
                  __float_as_uint(m));
}

// ---------------- head -----------------------------------------------------
__global__ __launch_bounds__(64) void head_kernel(
    const float* __restrict__ lin0w, const float* __restrict__ lin0b,
    const float* __restrict__ lin1w, const float* __restrict__ lin1b,
    float* __restrict__ out)
{
    __shared__ float pg[EMB];
    __shared__ float red[EMB];
    int g = blockIdx.x, o = threadIdx.x;
    float bo = lin0b[o];          // pre-wait: inputs only
    float w1 = lin1w[o];
    GDC_WAIT();
    pg[o] = g_pool[(size_t)g * EMB + o];
    __syncthreads();

    float h = bo;
#pragma unroll
    for (int i = 0; i < EMB; i++) h += pg[i] * lin0w[i * EMB + o];
    red[o] = h * w1;
    __syncthreads();
#pragma unroll
    for (int s = 32; s > 0; s >>= 1) {
        if (o < s) red[o] += red[o + s];
        __syncthreads();
    }
    if (o == 0) out[g] = red[0] + lin1b[0];
}

// ---------------- PDL launch helper ----------------------------------------
template <typename... Args>
static void launch_pdl(void (*func)(Args...), dim3 grid, dim3 block,
                       size_t smem, Args... args)
{
    cudaLaunchConfig_t cfg = {};
    cfg.gridDim = grid;
    cfg.blockDim = block;
    cfg.dynamicSmemBytes = smem;
    cfg.stream = 0;
    cudaLaunchAttribute attr[1];
    attr[0].id = cudaLaunchAttributeProgrammaticStreamSerialization;
    attr[0].val.programmaticStreamSerializationAllowed = 1;
    cfg.attrs = attr;
    cfg.numAttrs = 1;
    cudaLaunchKernelEx(&cfg, func, args...);
}

// ---------------- launch ----------------------------------------------------
extern "C" void kernel_launch(void* const* d_in, const int* in_sizes, int n_in,
                              void* d_out, int out_size)
{
    const float* x_p    = (const float*)d_in[0];
    const float* ea     = (const float*)d_in[2];
    const int*   ei     = (const int*)  d_in[4];
    const int*   batch  = (const int*)  d_in[5];
    const float* nn0_w1 = (const float*)d_in[6];
    const float* nn0_b1 = (const float*)d_in[7];
    const float* nn0_w2 = (const float*)d_in[8];
    const float* nn0_b2 = (const float*)d_in[9];
    const float* nn1_w1 = (const float*)d_in[10];
    const float* nn1_b1 = (const float*)d_in[11];
    const float* nn1_w2 = (const float*)d_in[12];
    const float* nn1_b2 = (const float*)d_in[13];
    const float* root0  = (const float*)d_in[14];
    const float* bias0  = (const float*)d_in[15];
    const float* root1  = (const float*)d_in[16];
    const float* bias1  = (const float*)d_in[17];
    const float* root2  = (const float*)d_in[18];
    const float* bias2  = (const float*)d_in[19];
    const float* lin0_w = (const float*)d_in[20];
    const float* lin0_b = (const float*)d_in[21];
    const float* lin1_w = (const float*)d_in[22];
    const float* lin1_b = (const float*)d_in[23];
    float* out = (float*)d_out;

    // smem: A(hi) 128*SD*2 + B(hi+lo) 2*64*SD*2 bytes
    size_t smem32 = 128 * 40 * 2 + 2 * 64 * 40 * 2;   // 20480
    size_t smem64 = 128 * 72 * 2 + 2 * 64 * 72 * 2;   // 36864

    dim3 gemm_grid(9, (NN + 127) / 128);
    int msg_blocks = EE / 16;

    // prep participates in PDL as a parent (releases gemm32 at start)
    launch_pdl(prep_kernel, dim3(TR_BLOCKS + EH_BLOCKS), dim3(256), (size_t)0,
               ea, nn0_w1, nn0_b1, nn0_w2, nn0_b2, nn1_w1, nn1_b1, nn1_w2, nn1_b2,
               root0, root1, root2);

    // ---- conv0 (A-stage overlaps prep; waits before B reads) ----
    launch_pdl(gemm_fused_kernel<32, 0>, gemm_grid, dim3(256), smem32, x_p, bias0);
    launch_pdl(edge_msg_kernel, dim3(msg_blocks), dim3(256), (size_t)0, ei, 0);

    // ---- conv1 ----
    launch_pdl(gemm_fused_kernel<64, 1>, gemm_grid, dim3(256), smem64,
               (const float*)nullptr, bias0);
    launch_pdl(edge_msg_kernel, dim3(msg_blocks), dim3(256), (size_t)0, ei, 1);

    // ---- conv2 ----
    launch_pdl(gemm_fused_kernel<64, 2>, gemm_grid, dim3(256), smem64,
               (const float*)nullptr, bias1);
    launch_pdl(edge_msg_kernel, dim3(msg_blocks), dim3(256), (size_t)0, ei, 2);

    // ---- pool (fused final combine) + head ----
    launch_pdl(pool_kernel, dim3((NN + 31) / 32), dim3(256), (size_t)0, batch, bias2);
    launch_pdl(head_kernel, dim3(NG), dim3(64), (size_t)0,
               lin0_w, lin0_b, lin1_w, lin1_b, out);
}